// round 4
// baseline (speedup 1.0000x reference)
#include <cuda_runtime.h>
#include <math.h>

#define B1n 4
#define B2n 1024
#define Rn  64
#define Tn  8192
#define Ln  256

// Each thread owns 4 consecutive l values. 256 threads = 64 l-threads x 4 r-groups
// (16 receivers each). Per-receiver {frac, packed-offset} hoisted to registers in
// two 8-wide chunks so the inner loop has no shared loads and LDGs front-batch.

__global__ void __launch_bounds__(Ln)
tof_predictor_kernel(const float* __restrict__ rec,        // (B1,R,T)
                     const float* __restrict__ samp,       // (B1,B2,3)
                     const float* __restrict__ emit,       // (3,)
                     const float* __restrict__ recv,       // (R,3)
                     float* __restrict__ out)              // (B1,B2)
{
    const int b2  = blockIdx.x;
    const int b1  = blockIdx.y;
    const int tid = threadIdx.x;

    __shared__ float2 s_pr[Rn];          // {frac, as_float((r*Tn+i0a)<<2 | d)}
    __shared__ float  s_s1[4 * Ln];      // per-group partial sums of lerp
    __shared__ float  s_s2[4 * Ln];      // per-group partial sums of lerp^2
    __shared__ float  s_red[16];

    // ---- precompute per-receiver base + frac (threads 0..63) ----
    const float fs_c = 96000.0f / 343.0f;
    if (tid < Rn) {
        const float* sp = samp + ((size_t)b1 * B2n + b2) * 3;
        float sx = sp[0], sy = sp[1], sz = sp[2];
        float ex = sx - emit[0], ey = sy - emit[1], ez = sz - emit[2];
        float d_e = sqrtf(ex * ex + ey * ey + ez * ez);
        const float* rp = recv + tid * 3;
        float rx = sx - rp[0], ry = sy - rp[1], rz = sz - rp[2];
        float d_r = sqrtf(rx * rx + ry * ry + rz * rz);
        float start = (d_e + d_r) * fs_c;
        int i0 = (int)floorf(start);
        i0 = min(max(i0, 0), Tn - 8 - Ln);          // never fires for this geometry
        float frac = start - (float)i0;             // in [0,1)
        int i0a = i0 & ~3;
        int d   = i0 & 3;
        int packed = ((tid * Tn + i0a) << 2) | d;
        s_pr[tid] = make_float2(frac, __int_as_float(packed));
    }
    __syncthreads();

    const int g = tid >> 6;        // r-group 0..3  -> handles r = g*16 .. g*16+15
    const int t = tid & 63;        // l-thread      -> l = 4t .. 4t+3

    const float* recb = rec + (size_t)b1 * Rn * Tn + 4 * t;

    float a0 = 0.f, a1 = 0.f, a2 = 0.f, a3 = 0.f;   // sum lerp per l
    float q0 = 0.f, q1 = 0.f, q2 = 0.f, q3 = 0.f;   // sum lerp^2 per l

    const int r_lo = g * 16;

#pragma unroll
    for (int c = 0; c < 2; ++c) {                    // two chunks of 8 receivers
        // hoist 8 {frac, off} pairs into registers: 4x LDS.128
        float fr[8];
        int   od[8];
        const float4* prv = (const float4*)&s_pr[r_lo + c * 8];
#pragma unroll
        for (int i = 0; i < 4; ++i) {
            float4 v = prv[i];
            fr[2 * i]     = v.x;  od[2 * i]     = __float_as_int(v.y);
            fr[2 * i + 1] = v.z;  od[2 * i + 1] = __float_as_int(v.w);
        }

#pragma unroll
        for (int i = 0; i < 8; ++i) {
            float f = fr[i];
            int   o = od[i];
            int   d = o & 3;
            const float4* p = (const float4*)(recb + (o >> 2));
            float4 A = __ldg(p);
            float4 B = __ldg(p + 1);

            float w0, w1, w2, w3, w4;
            if (d == 0)      { w0=A.x; w1=A.y; w2=A.z; w3=A.w; w4=B.x; }
            else if (d == 1) { w0=A.y; w1=A.z; w2=A.w; w3=B.x; w4=B.y; }
            else if (d == 2) { w0=A.z; w1=A.w; w2=B.x; w3=B.y; w4=B.z; }
            else             { w0=A.w; w1=B.x; w2=B.y; w3=B.z; w4=B.w; }

            float e0 = fmaf(f, w1 - w0, w0);
            float e1 = fmaf(f, w2 - w1, w1);
            float e2 = fmaf(f, w3 - w2, w2);
            float e3 = fmaf(f, w4 - w3, w3);
            a0 += e0; q0 = fmaf(e0, e0, q0);
            a1 += e1; q1 = fmaf(e1, e1, q1);
            a2 += e2; q2 = fmaf(e2, e2, q2);
            a3 += e3; q3 = fmaf(e3, e3, q3);
        }
    }

    // store per-group partials (16B-aligned vector stores)
    {
        float4* p1 = (float4*)&s_s1[g * Ln + 4 * t];
        float4* p2 = (float4*)&s_s2[g * Ln + 4 * t];
        *p1 = make_float4(a0, a1, a2, a3);
        *p2 = make_float4(q0, q1, q2, q3);
    }
    __syncthreads();

    // combine across the 4 r-groups: thread tid owns l = tid
    float S1 = s_s1[tid] + s_s1[Ln + tid] + s_s1[2 * Ln + tid] + s_s1[3 * Ln + tid];
    float S2 = s_s2[tid] + s_s2[Ln + tid] + s_s2[2 * Ln + tid] + s_s2[3 * Ln + tid];

    // Hann half-window at l = tid (computed in-register, no smem round-trip)
    float wl = 0.5f - 0.5f * cosf(3.14159265358979323846f * (float)tid * (1.0f / 255.0f));
    float sw1 = wl * S1;               // sum_r xw
    float sw2 = (wl * wl) * S2;        // sum_r xw^2

    float num_p = sw2;
    float den_p = (sw2 - sw1 * sw1 * (1.0f / (float)Rn)) * (1.0f / (float)(Rn - 1));

    // ---- block reduction of (num_p, den_p) over 256 threads ----
    const unsigned FULL = 0xFFFFFFFFu;
#pragma unroll
    for (int off = 16; off > 0; off >>= 1) {
        num_p += __shfl_down_sync(FULL, num_p, off);
        den_p += __shfl_down_sync(FULL, den_p, off);
    }
    const int warp = tid >> 5;
    const int lane = tid & 31;
    if (lane == 0) {
        s_red[warp * 2 + 0] = num_p;
        s_red[warp * 2 + 1] = den_p;
    }
    __syncthreads();
    if (warp == 0) {
        float n  = (lane < 8) ? s_red[lane * 2 + 0] : 0.0f;
        float dd = (lane < 8) ? s_red[lane * 2 + 1] : 0.0f;
#pragma unroll
        for (int off = 4; off > 0; off >>= 1) {
            n  += __shfl_down_sync(FULL, n, off);
            dd += __shfl_down_sync(FULL, dd, off);
        }
        if (lane == 0) {
            float num = n * (1.0f / ((float)Rn * (float)Ln));
            float den = dd * (1.0f / (float)Ln) + 0.001f;
            out[(size_t)b1 * B2n + b2] = num / den;
        }
    }
}

extern "C" void kernel_launch(void* const* d_in, const int* in_sizes, int n_in,
                              void* d_out, int out_size)
{
    const float* recordings         = (const float*)d_in[0];
    const float* sample_locations   = (const float*)d_in[1];
    const float* emitter_location   = (const float*)d_in[2];
    const float* receiver_locations = (const float*)d_in[3];
    float* out = (float*)d_out;

    dim3 grid(B2n, B1n);
    dim3 block(Ln);
    tof_predictor_kernel<<<grid, block>>>(recordings, sample_locations,
                                          emitter_location, receiver_locations, out);
}